// round 1
// baseline (speedup 1.0000x reference)
#include <cuda_runtime.h>

#define Bn 8
#define Cn 128
#define Hn 64
#define Wn 64
#define NPIX (Bn*Hn*Wn)          // 32768
#define COUT 128

// ---- scratch (allocation-free: __device__ globals) ----
__device__ __align__(16) float g_xt[Bn*Hn*Wn*Cn];     // NHWC copy of x (16 MB)
__device__ __align__(16) float g_wt[9*Cn*COUT];       // w transposed: [k][c][o]
__device__ __align__(16) float g_wofft[9*4*Cn];       // w_off transposed: [tap][oc][c] (oc 0..3 only)
__device__ __align__(16) float g_off[NPIX*4];         // per-pixel {off0, off1, s1, s2}

// ---------------------------------------------------------------------------
// Kernel 1: weight transposes (tiny)
// ---------------------------------------------------------------------------
__global__ void wtrans_kernel(const float* __restrict__ w,
                              const float* __restrict__ w_off) {
    int tid = blockIdx.x * 256 + threadIdx.x;
    if (tid < 9*Cn*COUT) {
        int k = tid / (Cn*COUT);
        int r = tid % (Cn*COUT);
        int c = r / COUT;
        int o = r % COUT;
        g_wt[tid] = w[(o*Cn + c)*9 + k];      // w: [o][c][3][3]
    }
    if (tid < 9*4*Cn) {
        int tap = tid / (4*Cn);
        int r   = tid % (4*Cn);
        int oc  = r / Cn;
        int c   = r % Cn;
        g_wofft[tid] = w_off[(oc*Cn + c)*9 + tap];   // w_off: [5][c][3][3], oc<4 used
    }
}

// ---------------------------------------------------------------------------
// Kernel 2: NCHW -> NHWC transpose of x (tiled through smem, both sides coalesced)
// grid (2, 4, B*H), block (32, 8)
// ---------------------------------------------------------------------------
__global__ void transpose_kernel(const float* __restrict__ x) {
    __shared__ float tile[32][33];
    int bh = blockIdx.z;
    int b = bh >> 6, h = bh & 63;
    int c0 = blockIdx.y * 32;
    int w0 = blockIdx.x * 32;
    int tx = threadIdx.x, ty = threadIdx.y;
    #pragma unroll
    for (int i = 0; i < 32; i += 8)
        tile[ty + i][tx] = x[((b*Cn + c0 + ty + i)*Hn + h)*Wn + w0 + tx];
    __syncthreads();
    #pragma unroll
    for (int i = 0; i < 32; i += 8)
        g_xt[((bh*Wn) + w0 + ty + i)*Cn + c0 + tx] = tile[tx][ty + i];
}

// ---------------------------------------------------------------------------
// Kernel 3: offset conv -> per-pixel params {off0, off1, s1=relu(off2)+1, s2=relu(off3)+1}
// one warp per pixel; 8 pixels per block
// ---------------------------------------------------------------------------
__global__ __launch_bounds__(256) void offset_kernel(const float* __restrict__ b_off) {
    __shared__ float sw[9*4*Cn];     // 18 KB
    int tid = threadIdx.x;
    for (int i = tid; i < 9*4*Cn; i += 256) sw[i] = g_wofft[i];
    __syncthreads();

    int warp = tid >> 5, lane = tid & 31;
    int pix = blockIdx.x * 8 + warp;
    int b   = pix >> 12;
    int rem = pix & 4095;
    int h   = rem >> 6, w = rem & 63;

    float a0 = 0.f, a1 = 0.f, a2 = 0.f, a3 = 0.f;
    const float4* xt4 = (const float4*)g_xt;

    #pragma unroll
    for (int tap = 0; tap < 9; tap++) {
        int dy = tap/3 - 1, dx = tap%3 - 1;
        int yy = h + dy, xx = w + dx;
        if (yy < 0 || yy >= Hn || xx < 0 || xx >= Wn) continue;
        float4 v = xt4[((b*Hn + yy)*Wn + xx)*(Cn/4) + lane];
        const float4* wv = (const float4*)&sw[tap*4*Cn];
        float4 w0v = wv[0*32 + lane];
        float4 w1v = wv[1*32 + lane];
        float4 w2v = wv[2*32 + lane];
        float4 w3v = wv[3*32 + lane];
        a0 += v.x*w0v.x + v.y*w0v.y + v.z*w0v.z + v.w*w0v.w;
        a1 += v.x*w1v.x + v.y*w1v.y + v.z*w1v.z + v.w*w1v.w;
        a2 += v.x*w2v.x + v.y*w2v.y + v.z*w2v.z + v.w*w2v.w;
        a3 += v.x*w3v.x + v.y*w3v.y + v.z*w3v.z + v.w*w3v.w;
    }
    #pragma unroll
    for (int s = 16; s; s >>= 1) {
        a0 += __shfl_xor_sync(0xffffffffu, a0, s);
        a1 += __shfl_xor_sync(0xffffffffu, a1, s);
        a2 += __shfl_xor_sync(0xffffffffu, a2, s);
        a3 += __shfl_xor_sync(0xffffffffu, a3, s);
    }
    if (lane == 0) {
        float4 r;
        r.x = a0 + b_off[0];
        r.y = a1 + b_off[1];
        r.z = fmaxf(a2 + b_off[2], 0.f) + 1.f;
        r.w = fmaxf(a3 + b_off[3], 0.f) + 1.f;
        ((float4*)g_off)[pix] = r;
    }
}

// ---------------------------------------------------------------------------
// Kernel 4: fused bilinear sample + GEMM.
// One block per (b, h) row: 64 pixels. 256 threads.
// Per k: stage w_k [c][o] (64 KB) into smem, build sampled tile s[p][c]
// (64 x 132 padded), then 8o x 4p register-tile GEMM.
// ---------------------------------------------------------------------------
#define SW_ELEMS   (Cn*COUT)          // 16384
#define SS_STRIDE  132
#define SS_ELEMS   (64*SS_STRIDE)     // 8448
#define SMEM_FLOATS (SW_ELEMS + SS_ELEMS + 64*4)
#define SMEM_BYTES  (SMEM_FLOATS*4)   // 100352 B

#define COMP(v,i) ((i)==0?(v).x:((i)==1?(v).y:((i)==2?(v).z:(v).w)))

__global__ __launch_bounds__(256, 2) void main_kernel(const float* __restrict__ bias,
                                                      float* __restrict__ out) {
    extern __shared__ float smem[];
    float* s_w   = smem;                       // [c][o]  128*128
    float* s_s   = smem + SW_ELEMS;            // [p][132]
    float* s_off = smem + SW_ELEMS + SS_ELEMS; // [64][4]

    int tid = threadIdx.x;
    int bh  = blockIdx.x;
    int b   = bh >> 6, h = bh & 63;

    if (tid < 64)
        ((float4*)s_off)[tid] = ((const float4*)g_off)[(bh << 6) + tid];

    float acc[8][4];
    #pragma unroll
    for (int i = 0; i < 8; i++)
        #pragma unroll
        for (int j = 0; j < 4; j++) acc[i][j] = 0.f;

    int sp = tid >> 2;         // sampling: pixel 0..63
    int sq = tid & 3;          // sampling: channel quarter (32 ch)
    int o0 = (tid & 15) * 8;   // gemm: 8 output channels
    int p0 = (tid >> 4) * 4;   // gemm: 4 pixels

    const float4* xt4 = (const float4*)g_xt;

    #pragma unroll 1
    for (int k = 0; k < 9; k++) {
        __syncthreads();   // prev GEMM done reading s_w/s_s; s_off ready (k=0)

        // ---- stage w_k ----
        {
            const float4* wsrc = (const float4*)(g_wt + k*SW_ELEMS);
            float4* wdst = (float4*)s_w;
            #pragma unroll
            for (int i = 0; i < 16; i++)
                wdst[tid + i*256] = wsrc[tid + i*256];
        }

        // ---- sample 32 channels of pixel sp ----
        {
            float off0 = s_off[sp*4+0], off1 = s_off[sp*4+1];
            float sc1  = s_off[sp*4+2], sc2  = s_off[sp*4+3];
            int by = k/3 - 1, bx = k%3 - 1;
            float sk = (by != 0 && bx != 0) ? sc1 : ((by == 0 && bx == 0) ? 0.f : sc2);
            float py = (float)h  + (float)by * sk + off0;
            float px = (float)sp + (float)bx * sk + off1;
            float fy = floorf(py), fx = floorf(px);
            float wy = py - fy,    wx = px - fx;
            int y0 = (int)fy, x0 = (int)fx;
            float cw0 = (1.f-wy)*(1.f-wx), cw1 = (1.f-wy)*wx;
            float cw2 = wy*(1.f-wx),       cw3 = wy*wx;
            float cw[4] = {cw0, cw1, cw2, cw3};

            float4 samp[8];
            #pragma unroll
            for (int i = 0; i < 8; i++) samp[i] = make_float4(0.f,0.f,0.f,0.f);

            #pragma unroll
            for (int j = 0; j < 4; j++) {
                int yc = y0 + (j >> 1);
                int xc = x0 + (j & 1);
                if (yc < 0 || yc >= Hn || xc < 0 || xc >= Wn) continue;
                const float4* src = xt4 + ((b*Hn + yc)*Wn + xc)*(Cn/4) + sq*8;
                float wj = cw[j];
                #pragma unroll
                for (int i = 0; i < 8; i++) {
                    float4 v = src[i];
                    samp[i].x += wj*v.x; samp[i].y += wj*v.y;
                    samp[i].z += wj*v.z; samp[i].w += wj*v.w;
                }
            }
            float* srow = s_s + sp*SS_STRIDE + sq*32;
            #pragma unroll
            for (int i = 0; i < 8; i++) ((float4*)srow)[i] = samp[i];
        }
        __syncthreads();

        // ---- GEMM: acc[oi][pj] += w_k[c][o0+oi] * s[p0+pj][c] ----
        #pragma unroll 1
        for (int cc = 0; cc < Cn; cc += 4) {
            float4 sv0 = *(const float4*)&s_s[(p0+0)*SS_STRIDE + cc];
            float4 sv1 = *(const float4*)&s_s[(p0+1)*SS_STRIDE + cc];
            float4 sv2 = *(const float4*)&s_s[(p0+2)*SS_STRIDE + cc];
            float4 sv3 = *(const float4*)&s_s[(p0+3)*SS_STRIDE + cc];
            #pragma unroll
            for (int jc = 0; jc < 4; jc++) {
                float4 wa = *(const float4*)&s_w[(cc+jc)*COUT + o0];
                float4 wb = *(const float4*)&s_w[(cc+jc)*COUT + o0 + 4];
                float t0 = COMP(sv0, jc), t1 = COMP(sv1, jc);
                float t2 = COMP(sv2, jc), t3 = COMP(sv3, jc);
                acc[0][0] += wa.x*t0; acc[0][1] += wa.x*t1; acc[0][2] += wa.x*t2; acc[0][3] += wa.x*t3;
                acc[1][0] += wa.y*t0; acc[1][1] += wa.y*t1; acc[1][2] += wa.y*t2; acc[1][3] += wa.y*t3;
                acc[2][0] += wa.z*t0; acc[2][1] += wa.z*t1; acc[2][2] += wa.z*t2; acc[2][3] += wa.z*t3;
                acc[3][0] += wa.w*t0; acc[3][1] += wa.w*t1; acc[3][2] += wa.w*t2; acc[3][3] += wa.w*t3;
                acc[4][0] += wb.x*t0; acc[4][1] += wb.x*t1; acc[4][2] += wb.x*t2; acc[4][3] += wb.x*t3;
                acc[5][0] += wb.y*t0; acc[5][1] += wb.y*t1; acc[5][2] += wb.y*t2; acc[5][3] += wb.y*t3;
                acc[6][0] += wb.z*t0; acc[6][1] += wb.z*t1; acc[6][2] += wb.z*t2; acc[6][3] += wb.z*t3;
                acc[7][0] += wb.w*t0; acc[7][1] += wb.w*t1; acc[7][2] += wb.w*t2; acc[7][3] += wb.w*t3;
            }
        }
    }

    // ---- epilogue: out NCHW ----
    #pragma unroll
    for (int oi = 0; oi < 8; oi++) {
        int o = o0 + oi;
        float bo = bias[o];
        float4 r = make_float4(acc[oi][0]+bo, acc[oi][1]+bo, acc[oi][2]+bo, acc[oi][3]+bo);
        *(float4*)&out[((b*COUT + o)*Hn + h)*Wn + p0] = r;
    }
}

// ---------------------------------------------------------------------------
extern "C" void kernel_launch(void* const* d_in, const int* in_sizes, int n_in,
                              void* d_out, int out_size) {
    const float* x     = (const float*)d_in[0];
    const float* w_off = (const float*)d_in[1];
    const float* b_off = (const float*)d_in[2];
    const float* w     = (const float*)d_in[3];
    const float* bias  = (const float*)d_in[4];
    float* out = (float*)d_out;

    cudaFuncSetAttribute(main_kernel, cudaFuncAttributeMaxDynamicSharedMemorySize, SMEM_BYTES);

    wtrans_kernel<<<(9*Cn*COUT + 255)/256, 256>>>(w, w_off);
    transpose_kernel<<<dim3(2, 4, Bn*Hn), dim3(32, 8)>>>(x);
    offset_kernel<<<NPIX/8, 256>>>(b_off);
    main_kernel<<<Bn*Hn, 256, SMEM_BYTES>>>(bias, out);
}